// round 1
// baseline (speedup 1.0000x reference)
#include <cuda_runtime.h>
#include <cstdint>

#define NNODES 768
#define NFACES 256
#define NTOT   1024
#define E0     6144
#define EF     1536
#define ETOT   9216
#define C      64
#define ROWCAP 192
#define COLCAP 64

// ---------------- device scratch (static; no cudaMalloc allowed) ----------------
__device__ float g_node_all[NTOT * C];        // [1024,64] node_e ++ face_e
__device__ float g_conn[ETOT * C];            // [9216,64] edge attributes
__device__ float g_adjn[NTOT * NTOT];         // dense A -> adjn (4MB)
__device__ float g_dinv[NTOT];
__device__ int   g_row_cnt[NTOT];
__device__ int   g_row_col[NTOT * ROWCAP];
__device__ float g_row_val[NTOT * ROWCAP];
__device__ int   g_col_cnt[NTOT];
__device__ int   g_col_edge[NTOT * COLCAP];   // edges grouped by dst
__device__ int   g_edge_src[ETOT];
__device__ float g_full1[67108864];           // [1024,1024,64] layer-1 output (268MB)

// ---------------- zero / init ----------------
__global__ void k_zero() {
    int idx = blockIdx.x * blockDim.x + threadIdx.x;
    int stride = gridDim.x * blockDim.x;
    for (int i = idx; i < NTOT * NTOT; i += stride) g_adjn[i] = 0.f;
    if (idx < NTOT) { g_col_cnt[idx] = 0; g_row_cnt[idx] = 0; }
}

// ---------------- small embedding MLPs: relu(relu(X@W1+b1)@W2+b2) ----------------
// dst: 0 -> g_node_all[0:768], 1 -> g_conn[0:6144], 2 -> g_node_all[768:1024]
__global__ __launch_bounds__(128) void k_embed(
    const float* __restrict__ X, int R, int Din,
    const float* __restrict__ W1, const float* __restrict__ b1,
    const float* __restrict__ W2, const float* __restrict__ b2, int dst)
{
    float* Y = (dst == 0) ? g_node_all : (dst == 1) ? g_conn : (g_node_all + NNODES * C);
    __shared__ float Xs[16 * 144];
    __shared__ float Hs[16 * C];
    int r0 = blockIdx.x * 16;
    int t = threadIdx.x;
    for (int idx = t; idx < 16 * Din; idx += 128) {
        int r = idx / Din, d = idx % Din;
        Xs[r * Din + d] = (r0 + r < R) ? X[(size_t)(r0 + r) * Din + d] : 0.f;
    }
    __syncthreads();
    int lr = t >> 3;          // 0..15 local row
    int c0 = (t & 7) * 8;     // 8 channels per thread
    float h[8];
#pragma unroll
    for (int q = 0; q < 8; q++) h[q] = b1[c0 + q];
    for (int d = 0; d < Din; d++) {
        float x = Xs[lr * Din + d];
        const float* w = W1 + d * C + c0;
#pragma unroll
        for (int q = 0; q < 8; q++) h[q] += x * w[q];
    }
#pragma unroll
    for (int q = 0; q < 8; q++) Hs[lr * C + c0 + q] = fmaxf(h[q], 0.f);
    __syncthreads();
    float y[8];
#pragma unroll
    for (int q = 0; q < 8; q++) y[q] = b2[c0 + q];
    for (int m = 0; m < C; m++) {
        float hm = Hs[lr * C + m];
        const float* w = W2 + m * C + c0;
#pragma unroll
        for (int q = 0; q < 8; q++) y[q] += hm * w[q];
    }
    if (r0 + lr < R) {
        float* yo = Y + (size_t)(r0 + lr) * C + c0;
#pragma unroll
        for (int q = 0; q < 8; q++) yo[q] = fmaxf(y[q], 0.f);
    }
}

// ---------------- fill conn rows for face edges (needs face embeddings) ----------------
__global__ void k_conn_face() {
    int idx = blockIdx.x * blockDim.x + threadIdx.x;
    if (idx >= 2 * EF * C) return;
    int e = E0 + idx / C;
    int m = idx % C;
    int f;
    if (e < E0 + EF) f = (e - E0) / 6;
    else { int r = e - (E0 + EF); f = (1535 - r) / 6; }
    g_conn[e * C + m] = g_node_all[(NNODES + f) * C + m];
}

// ---------------- edge list: src/dst, scatter A, per-dst column lists ----------------
__global__ void k_edges(const int* __restrict__ ei, const int* __restrict__ fn) {
    int e = blockIdx.x * blockDim.x + threadIdx.x;
    if (e >= ETOT) return;
    int s, d;
    if (e < E0)            { s = ei[e]; d = ei[E0 + e]; }
    else if (e < E0 + EF)  { int q = e - E0; s = fn[q]; d = NNODES + q / 6; }
    else                   { int r = e - (E0 + EF); int rr = 1535 - r; s = NNODES + rr / 6; d = fn[rr]; }
    g_edge_src[e] = s;
    atomicAdd(&g_adjn[s * NTOT + d], 1.0f);
    int p = atomicAdd(&g_col_cnt[d], 1);
    if (p < COLCAP) g_col_edge[d * COLCAP + p] = e;
}

__global__ void k_diag() {
    int i = blockIdx.x * blockDim.x + threadIdx.x;
    if (i < NTOT) g_adjn[i * NTOT + i] += 1.f;
}

// ---------------- degree -> dinv per row ----------------
__global__ __launch_bounds__(256) void k_deg() {
    int i = blockIdx.x;
    float s = 0.f;
    for (int j = threadIdx.x; j < NTOT; j += 256) s += g_adjn[i * NTOT + j];
    __shared__ float red[8];
#pragma unroll
    for (int o = 16; o > 0; o >>= 1) s += __shfl_down_sync(0xffffffffu, s, o);
    if ((threadIdx.x & 31) == 0) red[threadIdx.x >> 5] = s;
    __syncthreads();
    if (threadIdx.x == 0) {
        float tot = 0.f;
        for (int w = 0; w < 8; w++) tot += red[w];
        g_dinv[i] = (tot > 0.f) ? (1.f / sqrtf(tot)) : 0.f;
    }
}

// ---------------- scale A -> adjn in place, build per-row CSR ----------------
__global__ __launch_bounds__(256) void k_scale_csr() {
    int i = blockIdx.x;
    __shared__ int cnt;
    if (threadIdx.x == 0) cnt = 0;
    __syncthreads();
    float di = g_dinv[i];
    for (int j = threadIdx.x; j < NTOT; j += 256) {
        float v = g_adjn[i * NTOT + j];
        if (v != 0.f) {
            v *= di * g_dinv[j];
            g_adjn[i * NTOT + j] = v;
            int p = atomicAdd(&cnt, 1);
            if (p < ROWCAP) { g_row_col[i * ROWCAP + p] = j; g_row_val[i * ROWCAP + p] = v; }
        }
    }
    __syncthreads();
    if (threadIdx.x == 0) g_row_cnt[i] = min(cnt, ROWCAP);
}

// ---------------- layer 1: full1 = relu((adjn @ full0_sparse) @ plW0 + plb0) ----------------
// block = (kt in 0..15, i in 0..1023); computes full1[i, kt*64:+64, :]
__global__ __launch_bounds__(256) void k_layer1(
    const float* __restrict__ plW, const float* __restrict__ plb)
{
    const int kt = blockIdx.x;
    const int i  = blockIdx.y;
    const int t  = threadIdx.x;
    __shared__ float Hs[64 * 65];
    __shared__ int nf;
    __shared__ unsigned char flag[64];
    __shared__ int flist[64];
    if (t == 0) nf = 0;
    if (t < 64) flag[t] = 0;
    __syncthreads();

    const int kl = t & 63;
    const int m0 = (t >> 6) * 16;
    const int k  = kt * 64 + kl;

    float acc[16];
    bool fl = false;
    float aik = g_adjn[i * NTOT + k];
    if (aik != 0.f) {
        fl = true;
        const float* na = g_node_all + k * C + m0;
#pragma unroll
        for (int q = 0; q < 16; q++) acc[q] = aik * na[q];
    } else {
#pragma unroll
        for (int q = 0; q < 16; q++) acc[q] = 0.f;
    }
    int cc = g_col_cnt[k]; if (cc > COLCAP) cc = COLCAP;
    for (int c = 0; c < cc; c++) {
        int e = g_col_edge[k * COLCAP + c];
        float a = g_adjn[i * NTOT + g_edge_src[e]];
        if (a != 0.f) {
            fl = true;
            const float4* cp = (const float4*)(g_conn + e * C + m0);
#pragma unroll
            for (int q = 0; q < 4; q++) {
                float4 v = cp[q];
                acc[4*q+0] += a * v.x; acc[4*q+1] += a * v.y;
                acc[4*q+2] += a * v.z; acc[4*q+3] += a * v.w;
            }
        }
    }
#pragma unroll
    for (int q = 0; q < 16; q++) Hs[kl * 65 + m0 + q] = acc[q];
    if ((t >> 6) == 0 && fl) { flag[kl] = 1; int p = atomicAdd(&nf, 1); flist[p] = kl; }
    __syncthreads();

    size_t base = ((size_t)i * NTOT + (size_t)kt * 64) * C;
    // unflagged rows: h==0 -> relu(plb0) constant row
    if (!flag[kl]) {
#pragma unroll
        for (int q = 0; q < 16; q++)
            g_full1[base + (size_t)kl * C + m0 + q] = fmaxf(plb[m0 + q], 0.f);
    }
    // flagged rows: tiny GEMM (only ~2..12 rows per tile)
    int n = nf;
    int c = t & 63;
    for (int idx = t >> 6; idx < n; idx += 4) {
        int row = flist[idx];
        float y = plb[c];
        const float* Hrow = Hs + row * 65;
#pragma unroll 16
        for (int m = 0; m < 64; m++) y += Hrow[m] * plW[m * 64 + c];
        g_full1[base + (size_t)row * C + c] = fmaxf(y, 0.f);
    }
}

// ---------------- layer 2 (sparse einsum) + MLP + output MLP, fused ----------------
// block = (i, kt); out[i, kt*64:+64, 0:32]
__global__ __launch_bounds__(256) void k_layer2(
    const float* __restrict__ plW, const float* __restrict__ plb,
    const float* __restrict__ oW1, const float* __restrict__ ob1,
    const float* __restrict__ oW2, const float* __restrict__ ob2,
    float* __restrict__ out)
{
    const int i  = blockIdx.x;   // fastest -> concurrent blocks share kt -> L2 reuse on g_full1
    const int kt = blockIdx.y;
    const int t  = threadIdx.x;
    __shared__ float Hs[64 * 65];
    __shared__ float Gs[64 * 65];

    // Phase A: H2[k,m] = sum_{j in nbr(i)} a_ij * full1[j, kt*64+k, m]
    {
        const int kl = t & 63;
        const int m0 = (t >> 6) * 16;
        float acc[16];
#pragma unroll
        for (int q = 0; q < 16; q++) acc[q] = 0.f;
        int rn = g_row_cnt[i];
        const int*   rc = g_row_col + i * ROWCAP;
        const float* rv = g_row_val + i * ROWCAP;
        for (int r = 0; r < rn; r++) {
            int j = rc[r];
            float a = rv[r];
            const float4* p = (const float4*)(g_full1 + ((size_t)j * NTOT + (size_t)kt * 64 + kl) * C + m0);
#pragma unroll
            for (int q = 0; q < 4; q++) {
                float4 v = p[q];
                acc[4*q+0] += a * v.x; acc[4*q+1] += a * v.y;
                acc[4*q+2] += a * v.z; acc[4*q+3] += a * v.w;
            }
        }
#pragma unroll
        for (int q = 0; q < 16; q++) Hs[kl * 65 + m0 + q] = acc[q];
    }
    __syncthreads();

    // Phase B: Gs = relu(Hs @ plW1 + plb1)   [64x64]
    {
        int r0 = (t >> 4) * 4, c0 = (t & 15) * 4;
        float y[4][4];
#pragma unroll
        for (int a = 0; a < 4; a++) { y[a][0] = plb[c0]; y[a][1] = plb[c0+1]; y[a][2] = plb[c0+2]; y[a][3] = plb[c0+3]; }
        for (int m = 0; m < 64; m++) {
            float4 w = *(const float4*)(plW + m * 64 + c0);
#pragma unroll
            for (int a = 0; a < 4; a++) {
                float av = Hs[(r0 + a) * 65 + m];
                y[a][0] += av * w.x; y[a][1] += av * w.y; y[a][2] += av * w.z; y[a][3] += av * w.w;
            }
        }
#pragma unroll
        for (int a = 0; a < 4; a++)
#pragma unroll
            for (int b = 0; b < 4; b++) Gs[(r0 + a) * 65 + c0 + b] = fmaxf(y[a][b], 0.f);
    }
    __syncthreads();

    // Phase C: Hs = relu(Gs @ oW1 + ob1)     [64x64]
    {
        int r0 = (t >> 4) * 4, c0 = (t & 15) * 4;
        float y[4][4];
#pragma unroll
        for (int a = 0; a < 4; a++) { y[a][0] = ob1[c0]; y[a][1] = ob1[c0+1]; y[a][2] = ob1[c0+2]; y[a][3] = ob1[c0+3]; }
        for (int m = 0; m < 64; m++) {
            float4 w = *(const float4*)(oW1 + m * 64 + c0);
#pragma unroll
            for (int a = 0; a < 4; a++) {
                float av = Gs[(r0 + a) * 65 + m];
                y[a][0] += av * w.x; y[a][1] += av * w.y; y[a][2] += av * w.z; y[a][3] += av * w.w;
            }
        }
#pragma unroll
        for (int a = 0; a < 4; a++)
#pragma unroll
            for (int b = 0; b < 4; b++) Hs[(r0 + a) * 65 + c0 + b] = fmaxf(y[a][b], 0.f);
    }
    __syncthreads();

    // Phase D: OUT = Hs @ oW2 + ob2  [64x32], no relu
    {
        int r0 = (t >> 3) * 2, c0 = (t & 7) * 4;
        float y[2][4];
#pragma unroll
        for (int a = 0; a < 2; a++) { y[a][0] = ob2[c0]; y[a][1] = ob2[c0+1]; y[a][2] = ob2[c0+2]; y[a][3] = ob2[c0+3]; }
        for (int m = 0; m < 64; m++) {
            float4 w = *(const float4*)(oW2 + m * 32 + c0);
#pragma unroll
            for (int a = 0; a < 2; a++) {
                float av = Hs[(r0 + a) * 65 + m];
                y[a][0] += av * w.x; y[a][1] += av * w.y; y[a][2] += av * w.z; y[a][3] += av * w.w;
            }
        }
        size_t ob = ((size_t)i * NTOT + (size_t)kt * 64) * 32;
#pragma unroll
        for (int a = 0; a < 2; a++) {
            float4 v = make_float4(y[a][0], y[a][1], y[a][2], y[a][3]);
            *(float4*)(out + ob + (size_t)(r0 + a) * 32 + c0) = v;
        }
    }
}

// ---------------- launch ----------------
extern "C" void kernel_launch(void* const* d_in, const int* in_sizes, int n_in,
                              void* d_out, int out_size)
{
    const float* node_x = (const float*)d_in[0];
    const float* edge_x = (const float*)d_in[1];
    const float* face_x = (const float*)d_in[2];
    const float* nW1 = (const float*)d_in[3];  const float* nb1 = (const float*)d_in[4];
    const float* nW2 = (const float*)d_in[5];  const float* nb2 = (const float*)d_in[6];
    const float* eW1 = (const float*)d_in[7];  const float* eb1 = (const float*)d_in[8];
    const float* eW2 = (const float*)d_in[9];  const float* eb2 = (const float*)d_in[10];
    const float* fW1 = (const float*)d_in[11]; const float* fb1 = (const float*)d_in[12];
    const float* fW2 = (const float*)d_in[13]; const float* fb2 = (const float*)d_in[14];
    const float* oW1 = (const float*)d_in[15]; const float* ob1 = (const float*)d_in[16];
    const float* oW2 = (const float*)d_in[17]; const float* ob2 = (const float*)d_in[18];
    const float* plW = (const float*)d_in[19]; const float* plb = (const float*)d_in[20];
    const int* edge_index = (const int*)d_in[21];
    const int* face_nodes = (const int*)d_in[22];
    float* out = (float*)d_out;

    k_zero<<<512, 256>>>();
    k_embed<<<NNODES / 16, 128>>>(node_x, NNODES, 144, nW1, nb1, nW2, nb2, 0);
    k_embed<<<E0 / 16, 128>>>(edge_x, E0, 144, eW1, eb1, eW2, eb2, 1);
    k_embed<<<NFACES / 16, 128>>>(face_x, NFACES, 12, fW1, fb1, fW2, fb2, 2);
    k_conn_face<<<(2 * EF * C + 255) / 256, 256>>>();
    k_edges<<<(ETOT + 255) / 256, 256>>>(edge_index, face_nodes);
    k_diag<<<(NTOT + 255) / 256, 256>>>();
    k_deg<<<NTOT, 256>>>();
    k_scale_csr<<<NTOT, 256>>>();
    k_layer1<<<dim3(16, NTOT), 256>>>(plW, plb);                       // plW0, plb0
    k_layer2<<<dim3(NTOT, 16), 256>>>(plW + 4096, plb + 64,            // plW1, plb1
                                      oW1, ob1, oW2, ob2, out);
    (void)in_sizes; (void)n_in; (void)out_size;
}

// round 2
// speedup vs baseline: 1.5554x; 1.5554x over previous
#include <cuda_runtime.h>
#include <cstdint>

#define NNODES 768
#define NFACES 256
#define NTOT   1024
#define E0     6144
#define EF     1536
#define ETOT   9216
#define C      64
#define ROWCAP 192
#define COLCAP 64
#define NKT    16
#define HSTR   68   // shared row stride (floats), 16B-aligned, conflict-friendly

// ---------------- device scratch (static; no cudaMalloc allowed) ----------------
__device__ float g_node_all[NTOT * C];        // [1024,64] node_e ++ face_e
__device__ float g_conn[ETOT * C];            // [9216,64] edge attributes
__device__ float g_adjn[NTOT * NTOT];         // dense A -> adjn (4MB)
__device__ float g_dinv[NTOT];
__device__ float g_srow[NTOT];                // row sums of adjn
__device__ int   g_row_cnt[NTOT];
__device__ int   g_row_col[NTOT * ROWCAP];
__device__ float g_row_val[NTOT * ROWCAP];
__device__ int   g_col_cnt[NTOT];
__device__ int   g_col_edge[NTOT * COLCAP];   // edges grouped by dst
__device__ int   g_edge_src[ETOT];
// delta pool: segment (j,kt) has capacity 64 rows of 64 floats (== dense size, zero overflow risk)
__device__ float g_delta[67108864];           // [1024*16 segs][64 rows][64 ch]
__device__ unsigned char g_sidx[NTOT * NKT * 64];  // k_local per compacted entry
__device__ int   g_scnt[NTOT * NKT];               // entries per segment

// ---------------- zero / init ----------------
__global__ void k_zero() {
    int idx = blockIdx.x * blockDim.x + threadIdx.x;
    int stride = gridDim.x * blockDim.x;
    for (int i = idx; i < NTOT * NTOT; i += stride) g_adjn[i] = 0.f;
    if (idx < NTOT) { g_col_cnt[idx] = 0; g_row_cnt[idx] = 0; }
}

// ---------------- small embedding MLPs: relu(relu(X@W1+b1)@W2+b2) ----------------
__global__ __launch_bounds__(128) void k_embed(
    const float* __restrict__ X, int R, int Din,
    const float* __restrict__ W1, const float* __restrict__ b1,
    const float* __restrict__ W2, const float* __restrict__ b2, int dst)
{
    float* Y = (dst == 0) ? g_node_all : (dst == 1) ? g_conn : (g_node_all + NNODES * C);
    __shared__ float Xs[16 * 144];
    __shared__ float Hs[16 * C];
    int r0 = blockIdx.x * 16;
    int t = threadIdx.x;
    for (int idx = t; idx < 16 * Din; idx += 128) {
        int r = idx / Din, d = idx % Din;
        Xs[r * Din + d] = (r0 + r < R) ? X[(size_t)(r0 + r) * Din + d] : 0.f;
    }
    __syncthreads();
    int lr = t >> 3;
    int c0 = (t & 7) * 8;
    float h[8];
#pragma unroll
    for (int q = 0; q < 8; q++) h[q] = b1[c0 + q];
    for (int d = 0; d < Din; d++) {
        float x = Xs[lr * Din + d];
        const float* w = W1 + d * C + c0;
#pragma unroll
        for (int q = 0; q < 8; q++) h[q] += x * w[q];
    }
#pragma unroll
    for (int q = 0; q < 8; q++) Hs[lr * C + c0 + q] = fmaxf(h[q], 0.f);
    __syncthreads();
    float y[8];
#pragma unroll
    for (int q = 0; q < 8; q++) y[q] = b2[c0 + q];
    for (int m = 0; m < C; m++) {
        float hm = Hs[lr * C + m];
        const float* w = W2 + m * C + c0;
#pragma unroll
        for (int q = 0; q < 8; q++) y[q] += hm * w[q];
    }
    if (r0 + lr < R) {
        float* yo = Y + (size_t)(r0 + lr) * C + c0;
#pragma unroll
        for (int q = 0; q < 8; q++) yo[q] = fmaxf(y[q], 0.f);
    }
}

// ---------------- fill conn rows for face edges ----------------
__global__ void k_conn_face() {
    int idx = blockIdx.x * blockDim.x + threadIdx.x;
    if (idx >= 2 * EF * C) return;
    int e = E0 + idx / C;
    int m = idx % C;
    int f;
    if (e < E0 + EF) f = (e - E0) / 6;
    else { int r = e - (E0 + EF); f = (1535 - r) / 6; }
    g_conn[e * C + m] = g_node_all[(NNODES + f) * C + m];
}

// ---------------- edges: scatter A, per-dst column lists ----------------
__global__ void k_edges(const int* __restrict__ ei, const int* __restrict__ fn) {
    int e = blockIdx.x * blockDim.x + threadIdx.x;
    if (e >= ETOT) return;
    int s, d;
    if (e < E0)            { s = ei[e]; d = ei[E0 + e]; }
    else if (e < E0 + EF)  { int q = e - E0; s = fn[q]; d = NNODES + q / 6; }
    else                   { int r = e - (E0 + EF); int rr = 1535 - r; s = NNODES + rr / 6; d = fn[rr]; }
    g_edge_src[e] = s;
    atomicAdd(&g_adjn[s * NTOT + d], 1.0f);
    int p = atomicAdd(&g_col_cnt[d], 1);
    if (p < COLCAP) g_col_edge[d * COLCAP + p] = e;
}

__global__ void k_diag() {
    int i = blockIdx.x * blockDim.x + threadIdx.x;
    if (i < NTOT) g_adjn[i * NTOT + i] += 1.f;
}

// ---------------- degree -> dinv per row ----------------
__global__ __launch_bounds__(256) void k_deg() {
    int i = blockIdx.x;
    float s = 0.f;
    for (int j = threadIdx.x; j < NTOT; j += 256) s += g_adjn[i * NTOT + j];
    __shared__ float red[8];
#pragma unroll
    for (int o = 16; o > 0; o >>= 1) s += __shfl_down_sync(0xffffffffu, s, o);
    if ((threadIdx.x & 31) == 0) red[threadIdx.x >> 5] = s;
    __syncthreads();
    if (threadIdx.x == 0) {
        float tot = 0.f;
        for (int w = 0; w < 8; w++) tot += red[w];
        g_dinv[i] = (tot > 0.f) ? (1.f / sqrtf(tot)) : 0.f;
    }
}

// ---------------- scale A -> adjn in place, build per-row CSR + row sums ----------------
__global__ __launch_bounds__(256) void k_scale_csr() {
    int i = blockIdx.x;
    __shared__ int cnt;
    __shared__ float red[8];
    if (threadIdx.x == 0) cnt = 0;
    __syncthreads();
    float di = g_dinv[i];
    float sv = 0.f;
    for (int j = threadIdx.x; j < NTOT; j += 256) {
        float v = g_adjn[i * NTOT + j];
        if (v != 0.f) {
            v *= di * g_dinv[j];
            g_adjn[i * NTOT + j] = v;
            sv += v;
            int p = atomicAdd(&cnt, 1);
            if (p < ROWCAP) { g_row_col[i * ROWCAP + p] = j; g_row_val[i * ROWCAP + p] = v; }
        }
    }
#pragma unroll
    for (int o = 16; o > 0; o >>= 1) sv += __shfl_down_sync(0xffffffffu, sv, o);
    if ((threadIdx.x & 31) == 0) red[threadIdx.x >> 5] = sv;
    __syncthreads();
    if (threadIdx.x == 0) {
        float tot = 0.f;
        for (int w = 0; w < 8; w++) tot += red[w];
        g_srow[i] = tot;
        g_row_cnt[i] = min(cnt, ROWCAP);
    }
}

// ---------------- layer 1: compute ONLY the non-constant delta rows ----------------
// delta(j,k,:) = relu(h1 @ plW0 + plb0) - relu(plb0), stored compacted per (j,kt) segment.
// block = (kt, j)
__global__ __launch_bounds__(256) void k_layer1(
    const float* __restrict__ plW, const float* __restrict__ plb)
{
    const int kt = blockIdx.x;
    const int j  = blockIdx.y;
    const int t  = threadIdx.x;
    __shared__ float Hs[64 * 65];
    __shared__ int nf;
    __shared__ int flist[64];
    if (t == 0) nf = 0;
    __syncthreads();

    const int kl = t & 63;
    const int m0 = (t >> 6) * 16;
    const int k  = kt * 64 + kl;

    float acc[16];
    bool fl = false;
    float ajk = g_adjn[j * NTOT + k];
    if (ajk != 0.f) {
        fl = true;
        const float* na = g_node_all + k * C + m0;
#pragma unroll
        for (int q = 0; q < 16; q++) acc[q] = ajk * na[q];
    } else {
#pragma unroll
        for (int q = 0; q < 16; q++) acc[q] = 0.f;
    }
    int cc = g_col_cnt[k]; if (cc > COLCAP) cc = COLCAP;
    for (int c = 0; c < cc; c++) {
        int e = g_col_edge[k * COLCAP + c];
        float a = g_adjn[j * NTOT + g_edge_src[e]];
        if (a != 0.f) {
            fl = true;
            const float4* cp = (const float4*)(g_conn + e * C + m0);
#pragma unroll
            for (int q = 0; q < 4; q++) {
                float4 v = cp[q];
                acc[4*q+0] += a * v.x; acc[4*q+1] += a * v.y;
                acc[4*q+2] += a * v.z; acc[4*q+3] += a * v.w;
            }
        }
    }
#pragma unroll
    for (int q = 0; q < 16; q++) Hs[kl * 65 + m0 + q] = acc[q];
    if ((t >> 6) == 0 && fl) { int p = atomicAdd(&nf, 1); flist[p] = kl; }
    __syncthreads();

    const int seg = j * NKT + kt;
    const int n = nf;
    const int c = t & 63;
    const float crc = fmaxf(plb[c], 0.f);
    const size_t segbase = (size_t)seg * 64 * 64;
    for (int idx = t >> 6; idx < n; idx += 4) {
        int row = flist[idx];
        float y = plb[c];
        const float* Hrow = Hs + row * 65;
#pragma unroll 16
        for (int m = 0; m < 64; m++) y += Hrow[m] * plW[m * 64 + c];
        g_delta[segbase + (size_t)idx * 64 + c] = fmaxf(y, 0.f) - crc;
        if (c == 0) g_sidx[seg * 64 + idx] = (unsigned char)row;
    }
    if (t == 0) g_scnt[seg] = n;
}

// ---------------- layer 2 (const + delta gather) + MLP + output MLP, fused ----------------
// block = (i, kt); out[i, kt*64:+64, 0:32]
__global__ __launch_bounds__(256) void k_layer2(
    const float* __restrict__ plb0,
    const float* __restrict__ plW, const float* __restrict__ plb,
    const float* __restrict__ oW1, const float* __restrict__ ob1,
    const float* __restrict__ oW2, const float* __restrict__ ob2,
    float* __restrict__ out)
{
    const int i  = blockIdx.x;   // fastest -> concurrent blocks share kt slice in L2
    const int kt = blockIdx.y;
    const int t  = threadIdx.x;
    __shared__ float Hs[64 * HSTR];
    __shared__ float Gs[64 * HSTR];

    // Phase A: Hs[k,:] = s_i*cr + sum_{j in nbr(i)} a_ij * delta(j,k,:)
    {
        const int kl = t & 63;
        const int m0 = (t >> 6) * 16;
        const float sI = g_srow[i];
#pragma unroll
        for (int q = 0; q < 16; q++)
            Hs[kl * HSTR + m0 + q] = sI * fmaxf(plb0[m0 + q], 0.f);
        __syncthreads();

        const int rn = g_row_cnt[i];
        const int*   rc = g_row_col + i * ROWCAP;
        const float* rv = g_row_val + i * ROWCAP;
        const int p   = t >> 2;          // entry slot 0..63
        const int sub = (t & 3) * 16;    // channel quarter
        for (int r = 0; r < rn; r++) {
            int j = rc[r];
            float a = rv[r];
            int seg = j * NKT + kt;
            int cnt = g_scnt[seg];
            if (p < cnt) {
                int klq = g_sidx[seg * 64 + p];
                const float4* dp = (const float4*)(g_delta + ((size_t)seg * 64 + p) * 64 + sub);
                float* h = Hs + klq * HSTR + sub;
#pragma unroll
                for (int q = 0; q < 4; q++) {
                    float4 v = dp[q];
                    h[4*q+0] += a * v.x; h[4*q+1] += a * v.y;
                    h[4*q+2] += a * v.z; h[4*q+3] += a * v.w;
                }
            }
            __syncthreads();
        }
    }

    // Phase B: Gs = relu(Hs @ plW1 + plb1)   [64x64]
    {
        int r0 = (t >> 4) * 4, c0 = (t & 15) * 4;
        float y[4][4];
#pragma unroll
        for (int a = 0; a < 4; a++) { y[a][0] = plb[c0]; y[a][1] = plb[c0+1]; y[a][2] = plb[c0+2]; y[a][3] = plb[c0+3]; }
        for (int m = 0; m < 64; m++) {
            float4 w = *(const float4*)(plW + m * 64 + c0);
#pragma unroll
            for (int a = 0; a < 4; a++) {
                float av = Hs[(r0 + a) * HSTR + m];
                y[a][0] += av * w.x; y[a][1] += av * w.y; y[a][2] += av * w.z; y[a][3] += av * w.w;
            }
        }
#pragma unroll
        for (int a = 0; a < 4; a++)
#pragma unroll
            for (int b = 0; b < 4; b++) Gs[(r0 + a) * HSTR + c0 + b] = fmaxf(y[a][b], 0.f);
    }
    __syncthreads();

    // Phase C: Hs = relu(Gs @ oW1 + ob1)     [64x64]
    {
        int r0 = (t >> 4) * 4, c0 = (t & 15) * 4;
        float y[4][4];
#pragma unroll
        for (int a = 0; a < 4; a++) { y[a][0] = ob1[c0]; y[a][1] = ob1[c0+1]; y[a][2] = ob1[c0+2]; y[a][3] = ob1[c0+3]; }
        for (int m = 0; m < 64; m++) {
            float4 w = *(const float4*)(oW1 + m * 64 + c0);
#pragma unroll
            for (int a = 0; a < 4; a++) {
                float av = Gs[(r0 + a) * HSTR + m];
                y[a][0] += av * w.x; y[a][1] += av * w.y; y[a][2] += av * w.z; y[a][3] += av * w.w;
            }
        }
        __syncthreads();
#pragma unroll
        for (int a = 0; a < 4; a++)
#pragma unroll
            for (int b = 0; b < 4; b++) Hs[(r0 + a) * HSTR + c0 + b] = fmaxf(y[a][b], 0.f);
    }
    __syncthreads();

    // Phase D: OUT = Hs @ oW2 + ob2  [64x32], no relu
    {
        int r0 = (t >> 3) * 2, c0 = (t & 7) * 4;
        float y[2][4];
#pragma unroll
        for (int a = 0; a < 2; a++) { y[a][0] = ob2[c0]; y[a][1] = ob2[c0+1]; y[a][2] = ob2[c0+2]; y[a][3] = ob2[c0+3]; }
        for (int m = 0; m < 64; m++) {
            float4 w = *(const float4*)(oW2 + m * 32 + c0);
#pragma unroll
            for (int a = 0; a < 2; a++) {
                float av = Hs[(r0 + a) * HSTR + m];
                y[a][0] += av * w.x; y[a][1] += av * w.y; y[a][2] += av * w.z; y[a][3] += av * w.w;
            }
        }
        size_t ob = ((size_t)i * NTOT + (size_t)kt * 64) * 32;
#pragma unroll
        for (int a = 0; a < 2; a++) {
            float4 v = make_float4(y[a][0], y[a][1], y[a][2], y[a][3]);
            *(float4*)(out + ob + (size_t)(r0 + a) * 32 + c0) = v;
        }
    }
}

// ---------------- launch ----------------
extern "C" void kernel_launch(void* const* d_in, const int* in_sizes, int n_in,
                              void* d_out, int out_size)
{
    const float* node_x = (const float*)d_in[0];
    const float* edge_x = (const float*)d_in[1];
    const float* face_x = (const float*)d_in[2];
    const float* nW1 = (const float*)d_in[3];  const float* nb1 = (const float*)d_in[4];
    const float* nW2 = (const float*)d_in[5];  const float* nb2 = (const float*)d_in[6];
    const float* eW1 = (const float*)d_in[7];  const float* eb1 = (const float*)d_in[8];
    const float* eW2 = (const float*)d_in[9];  const float* eb2 = (const float*)d_in[10];
    const float* fW1 = (const float*)d_in[11]; const float* fb1 = (const float*)d_in[12];
    const float* fW2 = (const float*)d_in[13]; const float* fb2 = (const float*)d_in[14];
    const float* oW1 = (const float*)d_in[15]; const float* ob1 = (const float*)d_in[16];
    const float* oW2 = (const float*)d_in[17]; const float* ob2 = (const float*)d_in[18];
    const float* plW = (const float*)d_in[19]; const float* plb = (const float*)d_in[20];
    const int* edge_index = (const int*)d_in[21];
    const int* face_nodes = (const int*)d_in[22];
    float* out = (float*)d_out;

    k_zero<<<512, 256>>>();
    k_embed<<<NNODES / 16, 128>>>(node_x, NNODES, 144, nW1, nb1, nW2, nb2, 0);
    k_embed<<<E0 / 16, 128>>>(edge_x, E0, 144, eW1, eb1, eW2, eb2, 1);
    k_embed<<<NFACES / 16, 128>>>(face_x, NFACES, 12, fW1, fb1, fW2, fb2, 2);
    k_conn_face<<<(2 * EF * C + 255) / 256, 256>>>();
    k_edges<<<(ETOT + 255) / 256, 256>>>(edge_index, face_nodes);
    k_diag<<<(NTOT + 255) / 256, 256>>>();
    k_deg<<<NTOT, 256>>>();
    k_scale_csr<<<NTOT, 256>>>();
    k_layer1<<<dim3(NKT, NTOT), 256>>>(plW, plb);                        // plW0, plb0
    k_layer2<<<dim3(NTOT, NKT), 256>>>(plb,                              // plb0 (for cr)
                                       plW + 4096, plb + 64,             // plW1, plb1
                                       oW1, ob1, oW2, ob2, out);
    (void)in_sizes; (void)n_in; (void)out_size;
}